// round 6
// baseline (speedup 1.0000x reference)
#include <cuda_runtime.h>
#include <cuda_bf16.h>

#define NN   102400
#define BSEG 2048
#define HD   128
#define VOC  100000
#define NVv  99999

typedef unsigned long long ull;

// ---------------- scratch (device globals; no allocation allowed) ----------
__device__ float d_vn[BSEG * HD];
__device__ float d_w1vn[BSEG * HD];
__device__ float d_sg[BSEG * HD];
__device__ float d_sh[BSEG * HD];
__device__ int   d_last[BSEG];

// ---------------- helpers --------------------------------------------------
// batch may be int64 or int32. Viewed as i32 words: int32 case -> word[NN-1]
// is the last segment id == 2047 (all segments non-empty, sorted). int64
// case -> word[NN-1] is the high half of element (NN-1)/2, which is 0.
__device__ __forceinline__ int get_seg(const int* bw, int i) {
    return (bw[NN - 1] == 0) ? bw[2 * i] : bw[i];
}

__device__ __forceinline__ ull pk2(float v) {
    ull r; unsigned u = __float_as_uint(v);
    asm("mov.b64 %0, {%1,%2};" : "=l"(r) : "r"(u), "r"(u));
    return r;
}
__device__ __forceinline__ void fma2(ull& d, ull a, ull b) {
    asm("fma.rn.f32x2 %0, %1, %2, %0;" : "+l"(d) : "l"(a), "l"(b));
}
__device__ __forceinline__ float2 u2f(ull v) {
    unsigned lo, hi;
    asm("mov.b64 {%0,%1}, %2;" : "=r"(lo), "=r"(hi) : "l"(v));
    return make_float2(__uint_as_float(lo), __uint_as_float(hi));
}
__device__ __forceinline__ float sigmoidf_(float v) {
    return 1.f / (1.f + __expf(-v));
}

// ---------------- kernel 0: zero segment accumulator -----------------------
__global__ void k_zero() {
    d_sg[blockIdx.x * blockDim.x + threadIdx.x] = 0.f;
}

// ---------------- kernel 1: last node index of each (sorted) segment -------
__global__ void k_last(const int* __restrict__ bw) {
    int i = blockIdx.x * blockDim.x + threadIdx.x;
    if (i >= NN) return;
    int s = get_seg(bw, i);
    if (i == NN - 1 || get_seg(bw, i + 1) != s) d_last[s] = i;
}

// ---------------- kernel 2: v_n gather + w1_vn = v_n @ W1^T + b1 -----------
// 128 threads, 8 segments per block. W1 staged transposed in shared.
__global__ __launch_bounds__(128) void k_vn_w1(const float* __restrict__ x,
                                               const float* __restrict__ W1,
                                               const float* __restrict__ W1b) {
    extern __shared__ float sm[];
    float* W1T = sm;              // [128][129]: W1T[k*129+j] = W1[j*128+k]
    float* vs  = sm + 128 * 129;  // [8][128]
    int tid = threadIdx.x;
    int s0 = blockIdx.x * 8;

    for (int idx = tid; idx < HD * HD; idx += 128) {
        int j = idx >> 7, k = idx & 127;
        W1T[k * 129 + j] = W1[idx];
    }
    for (int idx = tid; idx < 8 * HD; idx += 128) {
        int s = idx >> 7, jj = idx & 127;
        float xv = x[(long long)d_last[s0 + s] * HD + jj];
        vs[s * HD + jj] = xv;
        d_vn[(s0 + s) * HD + jj] = xv;
    }
    __syncthreads();

    int j = tid;
    for (int s = 0; s < 8; s++) {
        float acc = W1b[j];
        #pragma unroll 8
        for (int k = 0; k < HD; k++) acc += W1T[k * 129 + j] * vs[s * HD + k];
        d_w1vn[(s0 + s) * HD + j] = acc;
    }
}

// ---------------- kernel 3: fused node stage -------------------------------
// 256 threads, 128 nodes per block. y = x@W2^T (FFMA2 tiled),
// h = sigmoid(y + w1vn[batch] + b2), alpha = h.q + qb,
// run-aggregated atomicAdd of alpha*x into d_sg.
__global__ __launch_bounds__(256, 1) void k_node(const float* __restrict__ x,
                                                 const int*   __restrict__ bw,
                                                 const float* __restrict__ W2,
                                                 const float* __restrict__ W2b,
                                                 const float* __restrict__ qw,
                                                 const float* __restrict__ qbp) {
    extern __shared__ float sm[];
    float* W2T     = sm;                    // [128][132]: W2T[k*132+n] = W2[n*128+k]
    float* Xs      = W2T + 128 * 132;       // [128][132]: Xs[t*132+k]
    float* alpha_s = Xs + 128 * 132;        // [128]
    int*   seg_s   = (int*)(alpha_s + 128); // [128]

    int tid = threadIdx.x;
    int node0 = blockIdx.x * 128;
    float qb = qbp[0];

    for (int idx = tid; idx < HD * HD; idx += 256) {
        int n = idx >> 7, k = idx & 127;
        W2T[k * 132 + n] = W2[idx];
    }
    for (int idx = tid; idx < 128 * HD; idx += 256) {
        int t = idx >> 7, k = idx & 127;
        Xs[t * 132 + k] = x[(long long)node0 * HD + idx];
    }
    if (tid < 128) {
        seg_s[tid] = get_seg(bw, node0 + tid);
        alpha_s[tid] = qb;
    }
    __syncthreads();

    int tr = tid >> 4, tc = tid & 15;
    // rows m = tr*4 + (i&3) + 64*(i>>2), i<8 ; col pairs n = tc*4 + 2*(p&1) + 64*(p>>1), p<4
    ull acc[8][4];
    #pragma unroll
    for (int i = 0; i < 8; i++)
        #pragma unroll
        for (int p = 0; p < 4; p++) acc[i][p] = 0ull;

    #pragma unroll 4
    for (int k = 0; k < HD; k++) {
        ull a2[8];
        #pragma unroll
        for (int i = 0; i < 8; i++) {
            int m = tr * 4 + (i & 3) + ((i >> 2) << 6);
            a2[i] = pk2(Xs[m * 132 + k]);
        }
        ull b2[4];
        #pragma unroll
        for (int p = 0; p < 4; p++) {
            int n = tc * 4 + ((p & 1) << 1) + ((p >> 1) << 6);
            b2[p] = *(const ull*)&W2T[k * 132 + n];
        }
        #pragma unroll
        for (int i = 0; i < 8; i++)
            #pragma unroll
            for (int p = 0; p < 4; p++) fma2(acc[i][p], a2[i], b2[p]);
    }

    // epilogue: sigmoid + alpha partials
    float w2bv[8], qwv[8];
    #pragma unroll
    for (int p = 0; p < 4; p++) {
        int n = tc * 4 + ((p & 1) << 1) + ((p >> 1) << 6);
        w2bv[2 * p] = W2b[n];  w2bv[2 * p + 1] = W2b[n + 1];
        qwv [2 * p] = qw[n];   qwv [2 * p + 1] = qw[n + 1];
    }
    #pragma unroll
    for (int i = 0; i < 8; i++) {
        int m = tr * 4 + (i & 3) + ((i >> 2) << 6);
        const float* wv = d_w1vn + (long long)seg_s[m] * HD;
        float part = 0.f;
        #pragma unroll
        for (int p = 0; p < 4; p++) {
            int n = tc * 4 + ((p & 1) << 1) + ((p >> 1) << 6);
            float2 y = u2f(acc[i][p]);
            float h0 = sigmoidf_(y.x + wv[n]     + w2bv[2 * p]);
            float h1 = sigmoidf_(y.y + wv[n + 1] + w2bv[2 * p + 1]);
            part += h0 * qwv[2 * p] + h1 * qwv[2 * p + 1];
        }
        atomicAdd(&alpha_s[m], part);
    }
    __syncthreads();

    // segment-run aggregation: one hidden column per thread (tid<128);
    // global atomics only at segment boundaries (~2-3 per block).
    if (tid < 128) {
        int j = tid;
        int cur = seg_s[0];
        float run = 0.f;
        for (int t = 0; t < 128; t++) {
            int s = seg_s[t];
            if (s != cur) {
                atomicAdd(&d_sg[cur * HD + j], run);
                run = 0.f; cur = s;
            }
            run += alpha_s[t] * Xs[t * 132 + j];
        }
        atomicAdd(&d_sg[cur * HD + j], run);
    }
}

// ---------------- kernel 4: s_h = [v_n, s_g] @ W3^T + b3 -------------------
__global__ __launch_bounds__(128) void k_sh(const float* __restrict__ W3,
                                            const float* __restrict__ W3b) {
    extern __shared__ float sm[];
    float* W3T = sm;              // [256][129]: W3T[k*129+j] = W3[j*256+k]
    float* cs  = sm + 256 * 129;  // [8][256]
    int tid = threadIdx.x;
    int s0 = blockIdx.x * 8;

    for (int idx = tid; idx < HD * 2 * HD; idx += 128) {
        int j = idx >> 8, k = idx & 255;
        W3T[k * 129 + j] = W3[idx];
    }
    for (int idx = tid; idx < 8 * HD; idx += 128) {
        int s = idx >> 7, j = idx & 127;
        cs[s * 256 + j]      = d_vn[(s0 + s) * HD + j];
        cs[s * 256 + HD + j] = d_sg[(s0 + s) * HD + j];
    }
    __syncthreads();

    int j = tid;
    for (int s = 0; s < 8; s++) {
        float acc = W3b[j];
        #pragma unroll 8
        for (int k = 0; k < 2 * HD; k++) acc += W3T[k * 129 + j] * cs[s * 256 + k];
        d_sh[(s0 + s) * HD + j] = acc;
    }
}

// ---------------- kernel 5: z = s_h @ E[1:]^T ------------------------------
// 128x128 tile per block, 8x8 per thread, f32x2-packed FFMA2 math.
__global__ __launch_bounds__(256, 1) void k_final(const float* __restrict__ E,
                                                  float* __restrict__ C) {
    extern __shared__ float sm[];
    float* As = sm;             // [128][132]: As[m*132+k]
    float* Bs = sm + 128 * 132; // [128][132]: Bs[k*132+n] = E[(n0+n+1)*128+k]
    int tid = threadIdx.x;
    int m0 = blockIdx.x * 128;
    int n0 = blockIdx.y * 128;

    for (int idx = tid; idx < 128 * HD; idx += 256) {
        int m = idx >> 7, k = idx & 127;
        As[m * 132 + k] = d_sh[m0 * HD + idx];
    }
    for (int idx = tid; idx < 128 * HD; idx += 256) {
        int n = idx >> 7, k = idx & 127;
        int gn = n0 + n;
        Bs[k * 132 + n] = (gn < NVv) ? E[(long long)(gn + 1) * HD + k] : 0.f;
    }
    __syncthreads();

    int tr = tid >> 4, tc = tid & 15;
    ull acc[8][4];
    #pragma unroll
    for (int i = 0; i < 8; i++)
        #pragma unroll
        for (int p = 0; p < 4; p++) acc[i][p] = 0ull;

    #pragma unroll 4
    for (int k = 0; k < HD; k++) {
        ull a2[8];
        #pragma unroll
        for (int i = 0; i < 8; i++) {
            int m = tr * 4 + (i & 3) + ((i >> 2) << 6);
            a2[i] = pk2(As[m * 132 + k]);
        }
        ull b2[4];
        #pragma unroll
        for (int p = 0; p < 4; p++) {
            int n = tc * 4 + ((p & 1) << 1) + ((p >> 1) << 6);
            b2[p] = *(const ull*)&Bs[k * 132 + n];
        }
        #pragma unroll
        for (int i = 0; i < 8; i++)
            #pragma unroll
            for (int p = 0; p < 4; p++) fma2(acc[i][p], a2[i], b2[p]);
    }

    // NVv is odd -> row base alternates 8B alignment; use scalar stores.
    #pragma unroll
    for (int i = 0; i < 8; i++) {
        int m = m0 + tr * 4 + (i & 3) + ((i >> 2) << 6);
        size_t row = (size_t)m * NVv;
        #pragma unroll
        for (int p = 0; p < 4; p++) {
            int n = n0 + tc * 4 + ((p & 1) << 1) + ((p >> 1) << 6);
            float2 v = u2f(acc[i][p]);
            if (n     < NVv) C[row + n]     = v.x;
            if (n + 1 < NVv) C[row + n + 1] = v.y;
        }
    }
}

// ---------------- launch ---------------------------------------------------
extern "C" void kernel_launch(void* const* d_in, const int* in_sizes, int n_in,
                              void* d_out, int out_size) {
    const float* x   = (const float*)d_in[0];   // session_embedding [N,H]
    const float* E   = (const float*)d_in[1];   // emb_weight [VOC,H]
    const float* W1  = (const float*)d_in[2];
    const float* W1b = (const float*)d_in[3];
    const float* W2  = (const float*)d_in[4];
    const float* W2b = (const float*)d_in[5];
    const float* qw  = (const float*)d_in[6];
    const float* qb  = (const float*)d_in[7];
    const float* W3  = (const float*)d_in[8];
    const float* W3b = (const float*)d_in[9];
    const int*   bw  = (const int*)d_in[10];    // batch (int32 or int64 view)
    float* out = (float*)d_out;

    const int smem_vn    = (128 * 129 + 8 * 128) * 4;
    const int smem_node  = (128 * 132 * 2 + 128) * 4 + 128 * 4;
    const int smem_sh    = (256 * 129 + 8 * 256) * 4;
    const int smem_final = (128 * 132 * 2) * 4;

    cudaFuncSetAttribute(k_vn_w1, cudaFuncAttributeMaxDynamicSharedMemorySize, smem_vn);
    cudaFuncSetAttribute(k_node,  cudaFuncAttributeMaxDynamicSharedMemorySize, smem_node);
    cudaFuncSetAttribute(k_sh,    cudaFuncAttributeMaxDynamicSharedMemorySize, smem_sh);
    cudaFuncSetAttribute(k_final, cudaFuncAttributeMaxDynamicSharedMemorySize, smem_final);

    k_zero<<<(BSEG * HD) / 256, 256>>>();
    k_last<<<(NN + 255) / 256, 256>>>(bw);
    k_vn_w1<<<BSEG / 8, 128, smem_vn>>>(x, W1, W1b);
    k_node<<<NN / 128, 256, smem_node>>>(x, bw, W2, W2b, qw, qb);
    k_sh<<<BSEG / 8, 128, smem_sh>>>(W3, W3b);
    dim3 gf(BSEG / 128, (NVv + 127) / 128);
    k_final<<<gf, 256, smem_final>>>(E, out);
}

// round 8
// speedup vs baseline: 1.5279x; 1.5279x over previous
#include <cuda_runtime.h>
#include <cuda_bf16.h>
#include <cstdint>

#define NN   102400
#define BSEG 2048
#define HD   128
#define VOC  100000
#define NVv  99999

typedef unsigned long long ull;

// ---------------- scratch (device globals; no allocation allowed) ----------
__device__ float d_vn[BSEG * HD];
__device__ float d_w1vn[BSEG * HD];
__device__ float d_sg[BSEG * HD];
__device__ float d_sh[BSEG * HD];
__device__ int   d_last[BSEG];

// ---------------- helpers --------------------------------------------------
__device__ __forceinline__ int get_seg(const int* bw, int i) {
    return (bw[NN - 1] == 0) ? bw[2 * i] : bw[i];
}
__device__ __forceinline__ ull pk2(float v) {
    ull r; unsigned u = __float_as_uint(v);
    asm("mov.b64 %0, {%1,%2};" : "=l"(r) : "r"(u), "r"(u));
    return r;
}
__device__ __forceinline__ void fma2(ull& d, ull a, ull b) {
    asm("fma.rn.f32x2 %0, %1, %2, %0;" : "+l"(d) : "l"(a), "l"(b));
}
__device__ __forceinline__ float2 u2f(ull v) {
    unsigned lo, hi;
    asm("mov.b64 {%0,%1}, %2;" : "=r"(lo), "=r"(hi) : "l"(v));
    return make_float2(__uint_as_float(lo), __uint_as_float(hi));
}
__device__ __forceinline__ float sigmoidf_(float v) {
    return 1.f / (1.f + __expf(-v));
}
__device__ __forceinline__ uint32_t smem_u32(const void* p) {
    uint32_t a;
    asm("{ .reg .u64 t; cvta.to.shared.u64 t, %1; cvt.u32.u64 %0, t; }" : "=r"(a) : "l"(p));
    return a;
}
// blocked atom layout for [rows][128 bf16]: atom = 8 rows x 64 bf16 (1KB),
// atoms: row-blocks fastest (16), then k-half. SW128 swizzle inside.
__device__ __forceinline__ uint32_t atom_off(int r, int k) {
    uint32_t b = ((r >> 3) + (k >> 6) * 16) * 1024 + (r & 7) * 128 + (k & 63) * 2;
    return b ^ ((b >> 3) & 0x70);
}
__device__ __forceinline__ void ldm4(uint32_t& r0, uint32_t& r1, uint32_t& r2,
                                     uint32_t& r3, uint32_t addr) {
    asm volatile("ldmatrix.sync.aligned.m8n8.x4.shared.b16 {%0,%1,%2,%3}, [%4];"
                 : "=r"(r0), "=r"(r1), "=r"(r2), "=r"(r3) : "r"(addr));
}
__device__ __forceinline__ void mma16816(float* d, const uint32_t* a,
                                         uint32_t b0, uint32_t b1) {
    asm volatile(
        "mma.sync.aligned.m16n8k16.row.col.f32.bf16.bf16.f32 "
        "{%0,%1,%2,%3}, {%4,%5,%6,%7}, {%8,%9}, {%0,%1,%2,%3};"
        : "+f"(d[0]), "+f"(d[1]), "+f"(d[2]), "+f"(d[3])
        : "r"(a[0]), "r"(a[1]), "r"(a[2]), "r"(a[3]), "r"(b0), "r"(b1));
}

// ---------------- kernel 0: zero segment accumulator -----------------------
__global__ void k_zero() {
    d_sg[blockIdx.x * blockDim.x + threadIdx.x] = 0.f;
}

// ---------------- kernel 1: last node index per segment --------------------
__global__ void k_last(const int* __restrict__ bw) {
    int i = blockIdx.x * blockDim.x + threadIdx.x;
    if (i >= NN) return;
    int s = get_seg(bw, i);
    if (i == NN - 1 || get_seg(bw, i + 1) != s) d_last[s] = i;
}

// ---------------- kernel 2: v_n gather + w1_vn -----------------------------
__global__ __launch_bounds__(128) void k_vn_w1(const float* __restrict__ x,
                                               const float* __restrict__ W1,
                                               const float* __restrict__ W1b) {
    extern __shared__ float sm[];
    float* W1T = sm;
    float* vs  = sm + 128 * 129;
    int tid = threadIdx.x;
    int s0 = blockIdx.x * 8;

    for (int idx = tid; idx < HD * HD; idx += 128) {
        int j = idx >> 7, k = idx & 127;
        W1T[k * 129 + j] = W1[idx];
    }
    for (int idx = tid; idx < 8 * HD; idx += 128) {
        int s = idx >> 7, jj = idx & 127;
        float xv = x[(long long)d_last[s0 + s] * HD + jj];
        vs[s * HD + jj] = xv;
        d_vn[(s0 + s) * HD + jj] = xv;
    }
    __syncthreads();

    int j = tid;
    for (int s = 0; s < 8; s++) {
        float acc = W1b[j];
        #pragma unroll 8
        for (int k = 0; k < HD; k++) acc += W1T[k * 129 + j] * vs[s * HD + k];
        d_w1vn[(s0 + s) * HD + j] = acc;
    }
}

// ---------------- kernel 3: fused node stage -------------------------------
__global__ __launch_bounds__(256, 1) void k_node(const float* __restrict__ x,
                                                 const int*   __restrict__ bw,
                                                 const float* __restrict__ W2,
                                                 const float* __restrict__ W2b,
                                                 const float* __restrict__ qw,
                                                 const float* __restrict__ qbp) {
    extern __shared__ float sm[];
    float* W2T     = sm;
    float* Xs      = W2T + 128 * 132;
    float* alpha_s = Xs + 128 * 132;
    int*   seg_s   = (int*)(alpha_s + 128);

    int tid = threadIdx.x;
    int node0 = blockIdx.x * 128;
    float qb = qbp[0];

    for (int idx = tid; idx < HD * HD; idx += 256) {
        int n = idx >> 7, k = idx & 127;
        W2T[k * 132 + n] = W2[idx];
    }
    for (int idx = tid; idx < 128 * HD; idx += 256) {
        int t = idx >> 7, k = idx & 127;
        Xs[t * 132 + k] = x[(long long)node0 * HD + idx];
    }
    if (tid < 128) {
        seg_s[tid] = get_seg(bw, node0 + tid);
        alpha_s[tid] = qb;
    }
    __syncthreads();

    int tr = tid >> 4, tc = tid & 15;
    ull acc[8][4];
    #pragma unroll
    for (int i = 0; i < 8; i++)
        #pragma unroll
        for (int p = 0; p < 4; p++) acc[i][p] = 0ull;

    #pragma unroll 4
    for (int k = 0; k < HD; k++) {
        ull a2[8];
        #pragma unroll
        for (int i = 0; i < 8; i++) {
            int m = tr * 4 + (i & 3) + ((i >> 2) << 6);
            a2[i] = pk2(Xs[m * 132 + k]);
        }
        ull b2[4];
        #pragma unroll
        for (int p = 0; p < 4; p++) {
            int n = tc * 4 + ((p & 1) << 1) + ((p >> 1) << 6);
            b2[p] = *(const ull*)&W2T[k * 132 + n];
        }
        #pragma unroll
        for (int i = 0; i < 8; i++)
            #pragma unroll
            for (int p = 0; p < 4; p++) fma2(acc[i][p], a2[i], b2[p]);
    }

    float w2bv[8], qwv[8];
    #pragma unroll
    for (int p = 0; p < 4; p++) {
        int n = tc * 4 + ((p & 1) << 1) + ((p >> 1) << 6);
        w2bv[2 * p] = W2b[n];  w2bv[2 * p + 1] = W2b[n + 1];
        qwv [2 * p] = qw[n];   qwv [2 * p + 1] = qw[n + 1];
    }
    #pragma unroll
    for (int i = 0; i < 8; i++) {
        int m = tr * 4 + (i & 3) + ((i >> 2) << 6);
        const float* wv = d_w1vn + (long long)seg_s[m] * HD;
        float part = 0.f;
        #pragma unroll
        for (int p = 0; p < 4; p++) {
            int n = tc * 4 + ((p & 1) << 1) + ((p >> 1) << 6);
            float2 y = u2f(acc[i][p]);
            float h0 = sigmoidf_(y.x + wv[n]     + w2bv[2 * p]);
            float h1 = sigmoidf_(y.y + wv[n + 1] + w2bv[2 * p + 1]);
            part += h0 * qwv[2 * p] + h1 * qwv[2 * p + 1];
        }
        atomicAdd(&alpha_s[m], part);
    }
    __syncthreads();

    if (tid < 128) {
        int j = tid;
        int cur = seg_s[0];
        float run = 0.f;
        for (int t = 0; t < 128; t++) {
            int s = seg_s[t];
            if (s != cur) {
                atomicAdd(&d_sg[cur * HD + j], run);
                run = 0.f; cur = s;
            }
            run += alpha_s[t] * Xs[t * 132 + j];
        }
        atomicAdd(&d_sg[cur * HD + j], run);
    }
}

// ---------------- kernel 4: s_h = [v_n, s_g] @ W3^T + b3 -------------------
__global__ __launch_bounds__(128) void k_sh(const float* __restrict__ W3,
                                            const float* __restrict__ W3b) {
    extern __shared__ float sm[];
    float* W3T = sm;
    float* cs  = sm + 256 * 129;
    int tid = threadIdx.x;
    int s0 = blockIdx.x * 8;

    for (int idx = tid; idx < HD * 2 * HD; idx += 128) {
        int j = idx >> 8, k = idx & 255;
        W3T[k * 129 + j] = W3[idx];
    }
    for (int idx = tid; idx < 8 * HD; idx += 128) {
        int s = idx >> 7, j = idx & 127;
        cs[s * 256 + j]      = d_vn[(s0 + s) * HD + j];
        cs[s * 256 + HD + j] = d_sg[(s0 + s) * HD + j];
    }
    __syncthreads();

    int j = tid;
    for (int s = 0; s < 8; s++) {
        float acc = W3b[j];
        #pragma unroll 8
        for (int k = 0; k < 2 * HD; k++) acc += W3T[k * 129 + j] * cs[s * 256 + k];
        d_sh[(s0 + s) * HD + j] = acc;
    }
}

// ---------------- kernel 5: z = s_h @ E[1:]^T via split-bf16 mma.sync ------
// 128x128 tile per CTA, 256 threads = 8 warps (4m x 2n), warp tile 32x64.
// 3 split products (hi*hi + hi*lo + lo*hi) accumulated in f32 HMMA.
#define SA_HI 0
#define SA_LO 32768
#define SB_HI 65536
#define SB_LO 98304
#define SMEM_TC 131072

__global__ __launch_bounds__(256, 1) void k_final_mma(const float* __restrict__ E,
                                                      float* __restrict__ C) {
    extern __shared__ char smem[];
    uint32_t sb = smem_u32(smem);
    int tid = threadIdx.x;
    int wid = tid >> 5, lane = tid & 31;
    int m0 = blockIdx.x * 128;          // m fastest -> E chunk L2 reuse
    int n0 = blockIdx.y * 128;

    // ---- stage A (s_h tile) hi/lo, blocked-atom SW128 layout ----
    for (int idx = tid; idx < 128 * 64; idx += 256) {
        int r = idx >> 6, c = idx & 63;             // k = 2c
        float2 v = *(const float2*)&d_sh[(m0 + r) * HD + 2 * c];
        __nv_bfloat16 h0 = __float2bfloat16(v.x);
        __nv_bfloat16 l0 = __float2bfloat16(v.x - __bfloat162float(h0));
        __nv_bfloat16 h1 = __float2bfloat16(v.y);
        __nv_bfloat16 l1 = __float2bfloat16(v.y - __bfloat162float(h1));
        uint32_t o = atom_off(r, 2 * c);
        __nv_bfloat162 ph; ph.x = h0; ph.y = h1;
        __nv_bfloat162 pl; pl.x = l0; pl.y = l1;
        *(__nv_bfloat162*)(smem + SA_HI + o) = ph;
        *(__nv_bfloat162*)(smem + SA_LO + o) = pl;
    }
    // ---- stage B (E rows n0+1 .. n0+128) hi/lo ----
    for (int idx = tid; idx < 128 * 64; idx += 256) {
        int r = idx >> 6, c = idx & 63;
        int gn = n0 + r;
        float2 v = make_float2(0.f, 0.f);
        if (gn < NVv) v = *(const float2*)&E[(long long)(gn + 1) * HD + 2 * c];
        __nv_bfloat16 h0 = __float2bfloat16(v.x);
        __nv_bfloat16 l0 = __float2bfloat16(v.x - __bfloat162float(h0));
        __nv_bfloat16 h1 = __float2bfloat16(v.y);
        __nv_bfloat16 l1 = __float2bfloat16(v.y - __bfloat162float(h1));
        uint32_t o = atom_off(r, 2 * c);
        __nv_bfloat162 ph; ph.x = h0; ph.y = h1;
        __nv_bfloat162 pl; pl.x = l0; pl.y = l1;
        *(__nv_bfloat162*)(smem + SB_HI + o) = ph;
        *(__nv_bfloat162*)(smem + SB_LO + o) = pl;
    }
    __syncthreads();

    // ---- mainloop ----
    int wm = (wid & 3) * 32;
    int wn = (wid >> 2) * 64;
    int lrow = lane & 15;               // ldmatrix row within 16-row tile
    int lk   = (lane >> 4) * 8;         // ldmatrix k-half within k16

    float acc[2][8][4];
    #pragma unroll
    for (int i = 0; i < 2; i++)
        #pragma unroll
        for (int j = 0; j < 8; j++)
            #pragma unroll
            for (int q = 0; q < 4; q++) acc[i][j][q] = 0.f;

    #pragma unroll 1
    for (int sp = 0; sp < 3; sp++) {
        uint32_t abase = sb + (sp == 2 ? SA_LO : SA_HI);
        uint32_t bbase = sb + (sp == 1 ? SB_LO : SB_HI);
        #pragma unroll
        for (int kt = 0; kt < 128; kt += 16) {
            uint32_t a[2][4], b[4][4];
            #pragma unroll
            for (int i = 0; i < 2; i++)
                ldm4(a[i][0], a[i][1], a[i][2], a[i][3],
                     abase + atom_off(wm + i * 16 + lrow, kt + lk));
            #pragma unroll
            for (int j = 0; j < 4; j++)
                ldm4(b[j][0], b[j][1], b[j][2], b[j][3],
                     bbase + atom_off(wn + j * 16 + lrow, kt + lk));
            #pragma unroll
            for (int i = 0; i < 2; i++)
                #pragma unroll
                for (int j8 = 0; j8 < 8; j8++) {
                    int pr = j8 >> 1, lo = j8 & 1;
                    mma16816(acc[i][j8], a[i], b[pr][lo], b[pr][lo + 2]);
                }
        }
    }
    __syncthreads();

    // ---- epilogue: frags -> padded smem -> aligned vector STG ----
    float* Cs = (float*)smem;           // [128][132]
    int g = lane >> 2, t = lane & 3;
    #pragma unroll
    for (int i = 0; i < 2; i++)
        #pragma unroll
        for (int j8 = 0; j8 < 8; j8++) {
            int row = wm + i * 16 + g;
            int col = wn + j8 * 8 + 2 * t;
            *(float2*)&Cs[row * 132 + col]       = make_float2(acc[i][j8][0], acc[i][j8][1]);
            *(float2*)&Cs[(row + 8) * 132 + col] = make_float2(acc[i][j8][2], acc[i][j8][3]);
        }
    __syncthreads();

    bool full = (n0 + 128 <= NVv);
    for (int r = wid; r < 128; r += 8) {
        size_t base = (size_t)(m0 + r) * NVv + n0;
        const float* src = &Cs[r * 132];
        if (full) {
            int head = (int)((4 - (base & 3)) & 3);
            if (lane < head) C[base + lane] = src[lane];
            int nb = (128 - head) >> 2;
            if (lane < nb) {
                int c0 = head + 4 * lane;
                float4 v = make_float4(src[c0], src[c0 + 1], src[c0 + 2], src[c0 + 3]);
                *(float4*)(C + base + c0) = v;
            }
            int done = head + nb * 4;
            int rem = 128 - done;
            if (lane < rem) C[base + done + lane] = src[done + lane];
        } else {
            for (int c = lane; c < 128; c += 32)
                if (n0 + c < NVv) C[base + c] = src[c];
        }
    }
}

// ---------------- launch ---------------------------------------------------
extern "C" void kernel_launch(void* const* d_in, const int* in_sizes, int n_in,
                              void* d_out, int out_size) {
    const float* x   = (const float*)d_in[0];
    const float* E   = (const float*)d_in[1];
    const float* W1  = (const float*)d_in[2];
    const float* W1b = (const float*)d_in[3];
    const float* W2  = (const float*)d_in[4];
    const float* W2b = (const float*)d_in[5];
    const float* qw  = (const float*)d_in[6];
    const float* qb  = (const float*)d_in[7];
    const float* W3  = (const float*)d_in[8];
    const float* W3b = (const float*)d_in[9];
    const int*   bw  = (const int*)d_in[10];
    float* out = (float*)d_out;

    const int smem_vn   = (128 * 129 + 8 * 128) * 4;
    const int smem_node = (128 * 132 * 2 + 128) * 4 + 128 * 4;
    const int smem_sh   = (256 * 129 + 8 * 256) * 4;

    cudaFuncSetAttribute(k_vn_w1,     cudaFuncAttributeMaxDynamicSharedMemorySize, smem_vn);
    cudaFuncSetAttribute(k_node,      cudaFuncAttributeMaxDynamicSharedMemorySize, smem_node);
    cudaFuncSetAttribute(k_sh,        cudaFuncAttributeMaxDynamicSharedMemorySize, smem_sh);
    cudaFuncSetAttribute(k_final_mma, cudaFuncAttributeMaxDynamicSharedMemorySize, SMEM_TC);

    k_zero<<<(BSEG * HD) / 256, 256>>>();
    k_last<<<(NN + 255) / 256, 256>>>(bw);
    k_vn_w1<<<BSEG / 8, 128, smem_vn>>>(x, W1, W1b);
    k_node<<<NN / 128, 256, smem_node>>>(x, bw, W2, W2b, qw, qb);
    k_sh<<<BSEG / 8, 128, smem_sh>>>(W3, W3b);
    dim3 gf(BSEG / 128, (NVv + 127) / 128);   // m fastest -> E L2 reuse
    k_final_mma<<<gf, 256, SMEM_TC>>>(E, out);
}

// round 9
// speedup vs baseline: 2.3191x; 1.5178x over previous
#include <cuda_runtime.h>
#include <cuda_bf16.h>
#include <cstdint>

#define NN   102400
#define BSEG 2048
#define HD   128
#define VOC  100000
#define NVv  99999
#define NTILE 782            // ceil(NVv/128)
#define NTB  8               // n-tiles per k_final CTA

typedef unsigned long long ull;

// ---------------- scratch (device globals; no allocation allowed) ----------
__device__ float d_vn[BSEG * HD];
__device__ float d_w1vn[BSEG * HD];
__device__ float d_sg[BSEG * HD];
__device__ float d_sh[BSEG * HD];
__device__ int   d_last[BSEG];
// pre-split, pre-swizzled operand images: per tile 64KB = hi(32KB)|lo(32KB)
__device__ __align__(16) char d_Esp[(size_t)NTILE * 65536];
__device__ __align__(16) char d_Asp[16 * 65536];

// ---------------- helpers --------------------------------------------------
__device__ __forceinline__ int get_seg(const int* bw, int i) {
    return (bw[NN - 1] == 0) ? bw[2 * i] : bw[i];
}
__device__ __forceinline__ ull pk2(float v) {
    ull r; unsigned u = __float_as_uint(v);
    asm("mov.b64 %0, {%1,%2};" : "=l"(r) : "r"(u), "r"(u));
    return r;
}
__device__ __forceinline__ void fma2(ull& d, ull a, ull b) {
    asm("fma.rn.f32x2 %0, %1, %2, %0;" : "+l"(d) : "l"(a), "l"(b));
}
__device__ __forceinline__ float2 u2f(ull v) {
    unsigned lo, hi;
    asm("mov.b64 {%0,%1}, %2;" : "=r"(lo), "=r"(hi) : "l"(v));
    return make_float2(__uint_as_float(lo), __uint_as_float(hi));
}
__device__ __forceinline__ float sigmoidf_(float v) {
    return 1.f / (1.f + __expf(-v));
}
__device__ __forceinline__ uint32_t smem_u32(const void* p) {
    uint32_t a;
    asm("{ .reg .u64 t; cvta.to.shared.u64 t, %1; cvt.u32.u64 %0, t; }" : "=r"(a) : "l"(p));
    return a;
}
// blocked atom layout for [128 rows][128 bf16]: atom = 8 rows x 64 bf16 (1KB)
__device__ __forceinline__ uint32_t atom_off(int r, int k) {
    uint32_t b = ((r >> 3) + (k >> 6) * 16) * 1024 + (r & 7) * 128 + (k & 63) * 2;
    return b ^ ((b >> 3) & 0x70);
}
__device__ __forceinline__ void ldm4(uint32_t& r0, uint32_t& r1, uint32_t& r2,
                                     uint32_t& r3, uint32_t addr) {
    asm volatile("ldmatrix.sync.aligned.m8n8.x4.shared.b16 {%0,%1,%2,%3}, [%4];"
                 : "=r"(r0), "=r"(r1), "=r"(r2), "=r"(r3) : "r"(addr));
}
__device__ __forceinline__ void mma16816(float* d, const uint32_t* a,
                                         uint32_t b0, uint32_t b1) {
    asm volatile(
        "mma.sync.aligned.m16n8k16.row.col.f32.bf16.bf16.f32 "
        "{%0,%1,%2,%3}, {%4,%5,%6,%7}, {%8,%9}, {%0,%1,%2,%3};"
        : "+f"(d[0]), "+f"(d[1]), "+f"(d[2]), "+f"(d[3])
        : "r"(a[0]), "r"(a[1]), "r"(a[2]), "r"(a[3]), "r"(b0), "r"(b1));
}
__device__ __forceinline__ void cp16(uint32_t dst, const char* src) {
    asm volatile("cp.async.cg.shared.global [%0], [%1], 16;"
                 :: "r"(dst), "l"(__cvta_generic_to_global(src)) : "memory");
}
#define CP_COMMIT() asm volatile("cp.async.commit_group;" ::: "memory")
#define CP_WAIT(n)  asm volatile("cp.async.wait_group %0;" :: "n"(n) : "memory")

// ---------------- kernel 0: zero segment accumulator -----------------------
__global__ void k_zero() {
    d_sg[blockIdx.x * blockDim.x + threadIdx.x] = 0.f;
}

// ---------------- kernel 1: last node index per segment --------------------
__global__ void k_last(const int* __restrict__ bw) {
    int i = blockIdx.x * blockDim.x + threadIdx.x;
    if (i >= NN) return;
    int s = get_seg(bw, i);
    if (i == NN - 1 || get_seg(bw, i + 1) != s) d_last[s] = i;
}

// ---------------- split/pre-swizzle kernels --------------------------------
__global__ void k_splitE(const float* __restrict__ E) {
    int tn = blockIdx.x;
    size_t base = (size_t)tn * 65536;
    for (int idx = threadIdx.x; idx < 128 * 64; idx += 256) {
        int r = idx >> 6, c = idx & 63;
        int gn = tn * 128 + r;
        float2 v = make_float2(0.f, 0.f);
        if (gn < NVv) v = *(const float2*)&E[(size_t)(gn + 1) * HD + 2 * c];
        __nv_bfloat16 h0 = __float2bfloat16(v.x);
        __nv_bfloat16 l0 = __float2bfloat16(v.x - __bfloat162float(h0));
        __nv_bfloat16 h1 = __float2bfloat16(v.y);
        __nv_bfloat16 l1 = __float2bfloat16(v.y - __bfloat162float(h1));
        uint32_t o = atom_off(r, 2 * c);
        __nv_bfloat162 ph; ph.x = h0; ph.y = h1;
        __nv_bfloat162 pl; pl.x = l0; pl.y = l1;
        *(__nv_bfloat162*)(d_Esp + base + o) = ph;
        *(__nv_bfloat162*)(d_Esp + base + 32768 + o) = pl;
    }
}
__global__ void k_splitA() {
    int tn = blockIdx.x;   // 16 m-tiles
    size_t base = (size_t)tn * 65536;
    for (int idx = threadIdx.x; idx < 128 * 64; idx += 256) {
        int r = idx >> 6, c = idx & 63;
        float2 v = *(const float2*)&d_sh[(size_t)(tn * 128 + r) * HD + 2 * c];
        __nv_bfloat16 h0 = __float2bfloat16(v.x);
        __nv_bfloat16 l0 = __float2bfloat16(v.x - __bfloat162float(h0));
        __nv_bfloat16 h1 = __float2bfloat16(v.y);
        __nv_bfloat16 l1 = __float2bfloat16(v.y - __bfloat162float(h1));
        uint32_t o = atom_off(r, 2 * c);
        __nv_bfloat162 ph; ph.x = h0; ph.y = h1;
        __nv_bfloat162 pl; pl.x = l0; pl.y = l1;
        *(__nv_bfloat162*)(d_Asp + base + o) = ph;
        *(__nv_bfloat162*)(d_Asp + base + 32768 + o) = pl;
    }
}

// ---------------- kernel 2: v_n gather + w1_vn -----------------------------
__global__ __launch_bounds__(128) void k_vn_w1(const float* __restrict__ x,
                                               const float* __restrict__ W1,
                                               const float* __restrict__ W1b) {
    extern __shared__ float sm[];
    float* W1T = sm;
    float* vs  = sm + 128 * 129;
    int tid = threadIdx.x;
    int s0 = blockIdx.x * 8;

    for (int idx = tid; idx < HD * HD; idx += 128) {
        int j = idx >> 7, k = idx & 127;
        W1T[k * 129 + j] = W1[idx];
    }
    for (int idx = tid; idx < 8 * HD; idx += 128) {
        int s = idx >> 7, jj = idx & 127;
        float xv = x[(long long)d_last[s0 + s] * HD + jj];
        vs[s * HD + jj] = xv;
        d_vn[(s0 + s) * HD + jj] = xv;
    }
    __syncthreads();

    int j = tid;
    for (int s = 0; s < 8; s++) {
        float acc = W1b[j];
        #pragma unroll 8
        for (int k = 0; k < HD; k++) acc += W1T[k * 129 + j] * vs[s * HD + k];
        d_w1vn[(s0 + s) * HD + j] = acc;
    }
}

// ---------------- kernel 3: fused node stage (64 nodes, 2 CTAs/SM) ---------
__global__ __launch_bounds__(256, 2) void k_node(const float* __restrict__ x,
                                                 const int*   __restrict__ bw,
                                                 const float* __restrict__ W2,
                                                 const float* __restrict__ W2b,
                                                 const float* __restrict__ qw,
                                                 const float* __restrict__ qbp) {
    extern __shared__ float sm[];
    float* W2T     = sm;                    // [128][132]: W2T[k*132+n] = W2[n*128+k]
    float* Xs      = W2T + 128 * 132;       // [64][132]
    float* alpha_s = Xs + 64 * 132;         // [64]
    int*   seg_s   = (int*)(alpha_s + 64);  // [64]

    int tid = threadIdx.x;
    int node0 = blockIdx.x * 64;
    float qb = qbp[0];

    for (int idx = tid; idx < HD * HD; idx += 256) {
        int n = idx >> 7, k = idx & 127;
        W2T[k * 132 + n] = W2[idx];
    }
    for (int idx = tid; idx < 64 * 32; idx += 256) {  // float4 staging
        int t = idx >> 5, k4 = idx & 31;
        float4 v = *(const float4*)&x[(size_t)(node0 + t) * HD + k4 * 4];
        *(float4*)&Xs[t * 132 + k4 * 4] = v;
    }
    if (tid < 64) {
        seg_s[tid] = get_seg(bw, node0 + tid);
        alpha_s[tid] = qb;
    }
    __syncthreads();

    int tr = tid >> 4, tc = tid & 15;   // rows m = tr*4+i (i<4); cols n = tc*2 + p*32
    ull acc[4][4];
    #pragma unroll
    for (int i = 0; i < 4; i++)
        #pragma unroll
        for (int p = 0; p < 4; p++) acc[i][p] = 0ull;

    #pragma unroll 4
    for (int k = 0; k < HD; k++) {
        ull a2[4];
        #pragma unroll
        for (int i = 0; i < 4; i++) a2[i] = pk2(Xs[(tr * 4 + i) * 132 + k]);
        ull b2[4];
        #pragma unroll
        for (int p = 0; p < 4; p++) b2[p] = *(const ull*)&W2T[k * 132 + tc * 2 + p * 32];
        #pragma unroll
        for (int i = 0; i < 4; i++)
            #pragma unroll
            for (int p = 0; p < 4; p++) fma2(acc[i][p], a2[i], b2[p]);
    }

    float w2bv[8], qwv[8];
    #pragma unroll
    for (int p = 0; p < 4; p++) {
        int n = tc * 2 + p * 32;
        w2bv[2 * p] = W2b[n];  w2bv[2 * p + 1] = W2b[n + 1];
        qwv [2 * p] = qw[n];   qwv [2 * p + 1] = qw[n + 1];
    }
    #pragma unroll
    for (int i = 0; i < 4; i++) {
        int m = tr * 4 + i;
        const float* wv = d_w1vn + (long long)seg_s[m] * HD;
        float part = 0.f;
        #pragma unroll
        for (int p = 0; p < 4; p++) {
            int n = tc * 2 + p * 32;
            float2 y = u2f(acc[i][p]);
            float h0 = sigmoidf_(y.x + wv[n]     + w2bv[2 * p]);
            float h1 = sigmoidf_(y.y + wv[n + 1] + w2bv[2 * p + 1]);
            part += h0 * qwv[2 * p] + h1 * qwv[2 * p + 1];
        }
        atomicAdd(&alpha_s[m], part);
    }
    __syncthreads();

    if (tid < 128) {
        int j = tid;
        int cur = seg_s[0];
        float run = 0.f;
        for (int t = 0; t < 64; t++) {
            int s = seg_s[t];
            if (s != cur) {
                atomicAdd(&d_sg[cur * HD + j], run);
                run = 0.f; cur = s;
            }
            run += alpha_s[t] * Xs[t * 132 + j];
        }
        atomicAdd(&d_sg[cur * HD + j], run);
    }
}

// ---------------- kernel 4: s_h = [v_n, s_g] @ W3^T + b3 -------------------
__global__ __launch_bounds__(128) void k_sh(const float* __restrict__ W3,
                                            const float* __restrict__ W3b) {
    extern __shared__ float sm[];
    float* W3T = sm;
    float* cs  = sm + 256 * 129;
    int tid = threadIdx.x;
    int s0 = blockIdx.x * 8;

    for (int idx = tid; idx < HD * 2 * HD; idx += 128) {
        int j = idx >> 8, k = idx & 255;
        W3T[k * 129 + j] = W3[idx];
    }
    for (int idx = tid; idx < 8 * HD; idx += 128) {
        int s = idx >> 7, j = idx & 127;
        cs[s * 256 + j]      = d_vn[(s0 + s) * HD + j];
        cs[s * 256 + HD + j] = d_sg[(s0 + s) * HD + j];
    }
    __syncthreads();

    int j = tid;
    for (int s = 0; s < 8; s++) {
        float acc = W3b[j];
        #pragma unroll 8
        for (int k = 0; k < 2 * HD; k++) acc += W3T[k * 129 + j] * cs[s * 256 + k];
        d_sh[(s0 + s) * HD + j] = acc;
    }
}

// ---------------- kernel 5: z = s_h @ E[1:]^T, pipelined HMMA --------------
// grid (16 m-tiles, 98 n-groups). A tile resident (64KB), B double-buffered
// (2x64KB) via cp.async; 3 split-products accumulated in f32 HMMA; direct STG.
#define SMEM_FIN (3 * 65536)

__global__ __launch_bounds__(256, 1) void k_final_p(float* __restrict__ C) {
    extern __shared__ char smem[];
    uint32_t sb = smem_u32(smem);
    int tid = threadIdx.x;
    int wid = tid >> 5, lane = tid & 31;
    int m0 = blockIdx.x * 128;
    int t0 = blockIdx.y * NTB;

    // stage A (resident) + prefetch first B tile, one commit group
    {
        const char* srcA = d_Asp + (size_t)blockIdx.x * 65536;
        for (int i = tid; i < 4096; i += 256) cp16(sb + i * 16, srcA + i * 16);
        const char* srcB = d_Esp + (size_t)t0 * 65536;
        for (int i = tid; i < 4096; i += 256) cp16(sb + 65536 + i * 16, srcB + i * 16);
        CP_COMMIT();
    }

    int wm = (wid & 3) * 32;
    int wn = (wid >> 2) * 64;
    int lrow = lane & 15;
    int lk   = (lane >> 4) * 8;
    int g4 = lane >> 2, t4 = lane & 3;

    for (int tt = 0; tt < NTB; tt++) {
        int tn = t0 + tt;
        if (tn >= NTILE) break;
        bool pre = (tt + 1 < NTB) && (tn + 1 < NTILE);
        if (pre) {
            uint32_t dbuf = sb + 65536 + ((tt + 1) & 1) * 65536;
            const char* src = d_Esp + (size_t)(tn + 1) * 65536;
            for (int i = tid; i < 4096; i += 256) cp16(dbuf + i * 16, src + i * 16);
            CP_COMMIT();
            CP_WAIT(1);
        } else {
            CP_WAIT(0);
        }
        __syncthreads();

        uint32_t sB = sb + 65536 + (tt & 1) * 65536;
        float acc[2][8][4];
        #pragma unroll
        for (int i = 0; i < 2; i++)
            #pragma unroll
            for (int j = 0; j < 8; j++)
                #pragma unroll
                for (int q = 0; q < 4; q++) acc[i][j][q] = 0.f;

        #pragma unroll 1
        for (int sp = 0; sp < 3; sp++) {
            uint32_t abase = sb + (sp == 2 ? 32768 : 0);
            uint32_t bbase = sB + (sp == 1 ? 32768 : 0);
            #pragma unroll
            for (int kt = 0; kt < 128; kt += 16) {
                uint32_t a[2][4], b[4][4];
                #pragma unroll
                for (int i = 0; i < 2; i++)
                    ldm4(a[i][0], a[i][1], a[i][2], a[i][3],
                         abase + atom_off(wm + i * 16 + lrow, kt + lk));
                #pragma unroll
                for (int j = 0; j < 4; j++)
                    ldm4(b[j][0], b[j][1], b[j][2], b[j][3],
                         bbase + atom_off(wn + j * 16 + lrow, kt + lk));
                #pragma unroll
                for (int i = 0; i < 2; i++)
                    #pragma unroll
                    for (int j8 = 0; j8 < 8; j8++) {
                        int pr = j8 >> 1, lo = j8 & 1;
                        mma16816(acc[i][j8], a[i], b[pr][lo], b[pr][lo + 2]);
                    }
            }
        }

        // epilogue: direct stores (32B sectors fully covered by quad-threads)
        bool full = (tn * 128 + 128 <= NVv);
        #pragma unroll
        for (int i = 0; i < 2; i++) {
            int r0 = m0 + wm + i * 16 + g4;
            size_t b0 = (size_t)r0 * NVv;
            size_t b1 = (size_t)(r0 + 8) * NVv;
            #pragma unroll
            for (int j8 = 0; j8 < 8; j8++) {
                int gn = tn * 128 + wn + j8 * 8 + 2 * t4;
                if (full) {
                    C[b0 + gn]     = acc[i][j8][0];
                    C[b0 + gn + 1] = acc[i][j8][1];
                    C[b1 + gn]     = acc[i][j8][2];
                    C[b1 + gn + 1] = acc[i][j8][3];
                } else {
                    if (gn < NVv)     { C[b0 + gn]     = acc[i][j8][0];
                                        C[b1 + gn]     = acc[i][j8][2]; }
                    if (gn + 1 < NVv) { C[b0 + gn + 1] = acc[i][j8][1];
                                        C[b1 + gn + 1] = acc[i][j8][3]; }
                }
            }
        }
        __syncthreads();   // all reads of buf done before next prefetch overwrites
    }
}

// ---------------- launch ---------------------------------------------------
extern "C" void kernel_launch(void* const* d_in, const int* in_sizes, int n_in,
                              void* d_out, int out_size) {
    const float* x   = (const float*)d_in[0];
    const float* E   = (const float*)d_in[1];
    const float* W1  = (const float*)d_in[2];
    const float* W1b = (const float*)d_in[3];
    const float* W2  = (const float*)d_in[4];
    const float* W2b = (const float*)d_in[5];
    const float* qw  = (const float*)d_in[6];
    const float* qb  = (const float*)d_in[7];
    const float* W3  = (const float*)d_in[8];
    const float* W3b = (const float*)d_in[9];
    const int*   bw  = (const int*)d_in[10];
    float* out = (float*)d_out;

    const int smem_vn   = (128 * 129 + 8 * 128) * 4;
    const int smem_node = (128 * 132 + 64 * 132 + 64) * 4 + 64 * 4;
    const int smem_sh   = (256 * 129 + 8 * 256) * 4;

    cudaFuncSetAttribute(k_vn_w1,   cudaFuncAttributeMaxDynamicSharedMemorySize, smem_vn);
    cudaFuncSetAttribute(k_node,    cudaFuncAttributeMaxDynamicSharedMemorySize, smem_node);
    cudaFuncSetAttribute(k_sh,      cudaFuncAttributeMaxDynamicSharedMemorySize, smem_sh);
    cudaFuncSetAttribute(k_final_p, cudaFuncAttributeMaxDynamicSharedMemorySize, SMEM_FIN);

    k_zero<<<(BSEG * HD) / 256, 256>>>();
    k_last<<<(NN + 255) / 256, 256>>>(bw);
    k_splitE<<<NTILE, 256>>>(E);
    k_vn_w1<<<BSEG / 8, 128, smem_vn>>>(x, W1, W1b);
    k_node<<<NN / 64, 256, smem_node>>>(x, bw, W2, W2b, qw, qb);
    k_sh<<<BSEG / 8, 128, smem_sh>>>(W3, W3b);
    k_splitA<<<16, 256>>>();
    dim3 gf(16, (NTILE + NTB - 1) / NTB);
    k_final_p<<<gf, 256, SMEM_FIN>>>(out);
}